// round 13
// baseline (speedup 1.0000x reference)
#include <cuda_runtime.h>
#include <cuda_bf16.h>
#include <cstdint>

// ============================================================
// Problem sizes (fixed by the dataset)
// ============================================================
static constexpr int MM = 16384;   // B*S tokens
static constexpr int KK = 2048;    // D_IN
static constexpr int NN = 2048;    // D_OUT

// -------- unified GEMM tiling: CTA tile 128x128, 128B rows --------
static constexpr int TM = 128;
static constexpr int TN = 128;
static constexpr int SK8  = 128;                 // int8 per stage row
static constexpr int SKBF = 64;                  // bf16 per stage row (same 128B)
static constexpr int IT8  = KK / SK8;            // 16
static constexpr int ITBF = KK / SKBF;           // 32
static constexpr int AST  = TM * 128;            // 16 KB
static constexpr int STGB = 2 * AST;             // 32 KB (A + B)
static constexpr int GEMM_SMEM = 2 * STGB;       // 64 KB (2 stages — R9-proven)

// tile pools: 2048 tiles of 128x128
static constexpr int N_BF = 1064;                // bf16 pool [0, N_BF)
static constexpr int N_S8 = 2048 - N_BF;         // s8 pool  [N_BF, 2048)
static constexpr int NPERS = 304;                // persistent CTAs (2 per SM)

// [0] = bf16 pool, [1] = s8 pool, [2+smid] = per-SM arrival, [200] = wabs done
__device__ unsigned g_ctr[260];

// ============================================================
// Device scratch (static — no allocation allowed)
// ============================================================
__device__ __align__(1024) int8_t g_act8[(size_t)MM * KK];            // 32 MB
__device__ __align__(1024) int8_t g_wq8[(size_t)NN * KK];             //  4 MB
__device__ __align__(1024) __nv_bfloat16 g_actbf[(size_t)MM * KK];    // 64 MB
__device__ __align__(1024) __nv_bfloat16 g_wqbf[(size_t)NN * KK];     //  8 MB
__device__ float g_rowscale[MM];    // amax/127 (wscale folded in at epilogue)
__device__ float g_wpart[NN];
__device__ float g_wscale;   // = max(mean|W|, eps) = 1/s_w
__device__ float g_sw;       // = s_w

// ============================================================
// PTX helpers
// ============================================================
__device__ __forceinline__ uint32_t smem_u32(const void* p) {
    uint32_t a;
    asm("{ .reg .u64 t; cvta.to.shared.u64 t, %1; cvt.u32.u64 %0, t; }" : "=r"(a) : "l"(p));
    return a;
}

#define CP_ASYNC16(smem_addr, gmem_ptr) \
    asm volatile("cp.async.cg.shared.global [%0], [%1], 16;" \
        :: "r"(smem_addr), "l"(gmem_ptr) : "memory")
#define CP_COMMIT() asm volatile("cp.async.commit_group;" ::: "memory")
#define CP_WAIT(n)  asm volatile("cp.async.wait_group %0;" :: "n"(n) : "memory")

#define MMA_S8(c, a, b) \
    asm volatile( \
        "mma.sync.aligned.m16n8k32.row.col.s32.s8.s8.s32 " \
        "{%0,%1,%2,%3}, {%4,%5,%6,%7}, {%8,%9}, {%0,%1,%2,%3};" \
        : "+r"((c)[0]), "+r"((c)[1]), "+r"((c)[2]), "+r"((c)[3]) \
        : "r"((a)[0]), "r"((a)[1]), "r"((a)[2]), "r"((a)[3]), \
          "r"((b)[0]), "r"((b)[1]))

#define MMA_BF16(c, a, b) \
    asm volatile( \
        "mma.sync.aligned.m16n8k16.row.col.f32.bf16.bf16.f32 " \
        "{%0,%1,%2,%3}, {%4,%5,%6,%7}, {%8,%9}, {%0,%1,%2,%3};" \
        : "+f"((c)[0]), "+f"((c)[1]), "+f"((c)[2]), "+f"((c)[3]) \
        : "r"((a)[0]), "r"((a)[1]), "r"((a)[2]), "r"((a)[3]), \
          "r"((b)[0]), "r"((b)[1]))

__device__ __forceinline__ uint32_t pack4_s8(float q0, float q1, float q2, float q3) {
    int i0 = (int)q0, i1 = (int)q1, i2 = (int)q2, i3 = (int)q3;
    return (uint32_t)(i0 & 255) | ((uint32_t)(i1 & 255) << 8) |
           ((uint32_t)(i2 & 255) << 16) | ((uint32_t)(i3 & 255) << 24);
}

__device__ __forceinline__ float warp_sum(float v) {
    #pragma unroll
    for (int o = 16; o > 0; o >>= 1) v += __shfl_xor_sync(0xFFFFFFFFu, v, o);
    return v;
}
__device__ __forceinline__ float warp_max(float v) {
    #pragma unroll
    for (int o = 16; o > 0; o >>= 1) v = fmaxf(v, __shfl_xor_sync(0xFFFFFFFFu, v, o));
    return v;
}

// ============================================================
// Kernel 1: per-row |W| sums; the LAST CTA to finish also computes
// s_w (merged wfinal — saves one kernel launch).
// ============================================================
__global__ void __launch_bounds__(256) wabs_kernel(const float* __restrict__ w) {
    __shared__ float red[8];
    __shared__ int sdone;
    int row = blockIdx.x, t = threadIdx.x, lane = t & 31, wi = t >> 5;
    const float4* wr = reinterpret_cast<const float4*>(w) + (size_t)row * (KK / 4);
    float4 a = wr[t], b = wr[256 + t];
    float s = fabsf(a.x) + fabsf(a.y) + fabsf(a.z) + fabsf(a.w)
            + fabsf(b.x) + fabsf(b.y) + fabsf(b.z) + fabsf(b.w);
    s = warp_sum(s);
    if (lane == 0) red[wi] = s;
    __syncthreads();
    if (t == 0) {
        float tot = 0.f;
        #pragma unroll
        for (int i = 0; i < 8; i++) tot += red[i];
        g_wpart[row] = tot;
        __threadfence();
        unsigned d = atomicAdd(&g_ctr[200], 1u);
        sdone = (d == (unsigned)(NN - 1)) ? 1 : 0;
    }
    __syncthreads();
    if (sdone) {
        // final reduction (formerly wfinal_kernel), deterministic order
        float fs = 0.f;
        #pragma unroll
        for (int i = 0; i < NN / 256; i++) fs += g_wpart[t + i * 256];
        fs = warp_sum(fs);
        if (lane == 0) red[wi] = fs;
        __syncthreads();
        if (t == 0) {
            float tot = 0.f;
            #pragma unroll
            for (int i = 0; i < 8; i++) tot += red[i];
            float mean = tot * (1.0f / ((float)NN * (float)KK));
            float ws = fmaxf(mean, 1e-8f);
            g_wscale = ws;         // 1/s_w
            g_sw = 1.0f / ws;      // s_w
        }
    }
}

// Kernel 2: ternarize weight -> int8 {-1,0,1} AND bf16 copies
__global__ void __launch_bounds__(256) ternarize_kernel(const float* __restrict__ w) {
    int i = blockIdx.x * 256 + threadIdx.x;   // float4 index, total NN*KK/4
    float sw = g_sw;
    float4 v = reinterpret_cast<const float4*>(w)[i];
    float t0 = fminf(fmaxf(rintf(sw * v.x), -1.f), 1.f);
    float t1 = fminf(fmaxf(rintf(sw * v.y), -1.f), 1.f);
    float t2 = fminf(fmaxf(rintf(sw * v.z), -1.f), 1.f);
    float t3 = fminf(fmaxf(rintf(sw * v.w), -1.f), 1.f);
    reinterpret_cast<uint32_t*>(g_wq8)[i] = pack4_s8(t0, t1, t2, t3);
    __nv_bfloat162 p0, p1;
    p0.x = __float2bfloat16(t0); p0.y = __float2bfloat16(t1);
    p1.x = __float2bfloat16(t2); p1.y = __float2bfloat16(t3);
    __nv_bfloat162* dst = reinterpret_cast<__nv_bfloat162*>(g_wqbf);
    dst[2 * i]     = p0;
    dst[2 * i + 1] = p1;
}

// ============================================================
// Kernel 3: LayerNorm + per-token int8 fake-quant -> int8 + bf16 + row scale
// ============================================================
__global__ void __launch_bounds__(128) ln_quant_kernel(const float* __restrict__ x) {
    __shared__ float ssum[4], ssq[4], smx[4];
    int row = blockIdx.x, t = threadIdx.x, lane = t & 31, wi = t >> 5;
    const float4* xr = reinterpret_cast<const float4*>(x) + (size_t)row * (KK / 4);
    float4 v[4];
    #pragma unroll
    for (int i = 0; i < 4; i++) v[i] = xr[t + 128 * i];

    float s = 0.f;
    #pragma unroll
    for (int i = 0; i < 4; i++) s += v[i].x + v[i].y + v[i].z + v[i].w;
    s = warp_sum(s);
    if (lane == 0) ssum[wi] = s;
    __syncthreads();
    float mu = (ssum[0] + ssum[1] + ssum[2] + ssum[3]) * (1.0f / (float)KK);

    float d[16];
    #pragma unroll
    for (int i = 0; i < 4; i++) {
        d[4*i+0] = v[i].x - mu; d[4*i+1] = v[i].y - mu;
        d[4*i+2] = v[i].z - mu; d[4*i+3] = v[i].w - mu;
    }
    float sq = 0.f, mx = 0.f;
    #pragma unroll
    for (int i = 0; i < 16; i++) { sq += d[i] * d[i]; mx = fmaxf(mx, fabsf(d[i])); }
    sq = warp_sum(sq); mx = warp_max(mx);
    if (lane == 0) { ssq[wi] = sq; smx[wi] = mx; }
    __syncthreads();
    float var = (ssq[0] + ssq[1] + ssq[2] + ssq[3]) * (1.0f / (float)KK);
    float r = 1.0f / sqrtf(var + 1e-8f);
    float amax = fmaxf(r * fmaxf(fmaxf(smx[0], smx[1]), fmaxf(smx[2], smx[3])), 1e-8f);
    float sact = 127.0f / amax;
    if (t == 0) g_rowscale[row] = amax * (1.0f / 127.0f);   // wscale folded in later

    float sr = sact * r;
    uint32_t* arow = reinterpret_cast<uint32_t*>(g_act8 + (size_t)row * KK);
    __nv_bfloat162* brow = reinterpret_cast<__nv_bfloat162*>(g_actbf + (size_t)row * KK);
    #pragma unroll
    for (int i = 0; i < 4; i++) {
        float q0 = fminf(fmaxf(rintf(sr * d[4*i+0]), -128.f), 127.f);
        float q1 = fminf(fmaxf(rintf(sr * d[4*i+1]), -128.f), 127.f);
        float q2 = fminf(fmaxf(rintf(sr * d[4*i+2]), -128.f), 127.f);
        float q3 = fminf(fmaxf(rintf(sr * d[4*i+3]), -128.f), 127.f);
        int idx = t + 128 * i;
        arow[idx] = pack4_s8(q0, q1, q2, q3);
        __nv_bfloat162 p0, p1;
        p0.x = __float2bfloat16(q0); p0.y = __float2bfloat16(q1);
        p1.x = __float2bfloat16(q2); p1.y = __float2bfloat16(q3);
        brow[2 * idx]     = p0;
        brow[2 * idx + 1] = p1;
    }
}

// ============================================================
// Kernel 4: persistent dual-engine GEMM (exact R9 mainloop: 2-stage,
// CP_WAIT(1), unconditional commit). Each SM hosts one s8 CTA + one
// bf16 CTA (smid arrival parity); two atomic tile pools with
// cross-type stealing at the tail.
// ============================================================
__global__ void __launch_bounds__(256, 2)
gemm_pers_kernel(const float* __restrict__ bias, float* __restrict__ out) {
    extern __shared__ __align__(128) char smem[];
    const uint32_t sbase = smem_u32(smem);
    const int tid = threadIdx.x, lane = tid & 31, wid = tid >> 5;
    const int wm = wid >> 2, wn = wid & 3;         // warp grid 2x4, warp tile 64x32
    __shared__ int s_type, s_tile;

    if (tid == 0) {
        uint32_t smid;
        asm("mov.u32 %0, %%smid;" : "=r"(smid));
        unsigned idx = atomicAdd(&g_ctr[2 + smid], 1u);
        s_type = (int)(idx & 1u);                  // 0 = bf16, 1 = s8
    }
    __syncthreads();
    const int type = s_type;
    const float wsc = g_wscale;

    const int row_a = wm * 64;
    const int row_b = wn * 32;

    for (;;) {
        if (tid == 0) {
            int tile = -1;
            if (type == 0) {
                unsigned t = atomicAdd(&g_ctr[0], 1u);
                if (t < N_BF) tile = (int)t;
                else {
                    unsigned u = atomicAdd(&g_ctr[1], 1u);
                    if (u < N_S8) tile = N_BF + (int)u;
                }
            } else {
                unsigned t = atomicAdd(&g_ctr[1], 1u);
                if (t < N_S8) tile = N_BF + (int)t;
                else {
                    unsigned u = atomicAdd(&g_ctr[0], 1u);
                    if (u < N_BF) tile = (int)u;
                }
            }
            s_tile = tile;
        }
        __syncthreads();
        const int tile = s_tile;
        if (tile < 0) break;
        const int m0 = (tile >> 4) * TM;
        const int n0 = (tile & 15) * TN;

        if (type == 0) {
            // ---------------- bf16 engine ----------------
            const __nv_bfloat16* Ag = g_actbf + (size_t)m0 * KK;
            const __nv_bfloat16* Bg = g_wqbf + (size_t)n0 * KK;
            float acc[4][4][4];
            #pragma unroll
            for (int i = 0; i < 4; i++)
                #pragma unroll
                for (int j = 0; j < 4; j++)
                    #pragma unroll
                    for (int k = 0; k < 4; k++) acc[i][j][k] = 0.f;

            auto load_stage = [&](int it, int s) {
                uint32_t As = sbase + s * STGB;
                uint32_t Bs = As + AST;
                #pragma unroll
                for (int i = 0; i < 4; i++) {
                    int cc = tid + i * 256;
                    int row = cc >> 3, u = cc & 7;
                    uint32_t so = row * 128 + ((u ^ (row & 7)) << 4);
                    CP_ASYNC16(As + so, Ag + (size_t)row * KK + it * SKBF + u * 8);
                    CP_ASYNC16(Bs + so, Bg + (size_t)row * KK + it * SKBF + u * 8);
                }
            };

            load_stage(0, 0); CP_COMMIT();
            load_stage(1, 1); CP_COMMIT();

            for (int it = 0; it < ITBF; ++it) {
                int s = it & 1;
                CP_WAIT(1);
                __syncthreads();
                uint32_t As = sbase + s * STGB;
                uint32_t Bs = As + AST;
                #pragma unroll
                for (int kk = 0; kk < 4; ++kk) {    // 4 x K=16
                    uint32_t a[4][4];
                    #pragma unroll
                    for (int mi = 0; mi < 4; mi++) {
                        int row0 = row_a + mi * 16 + (lane >> 2);
                        #pragma unroll
                        for (int r = 0; r < 4; r++) {
                            int row = row0 + ((r & 1) << 3);
                            int u = kk * 2 + (r >> 1);
                            uint32_t addr = As + row * 128 + ((u ^ (row & 7)) << 4) + ((lane & 3) << 2);
                            asm volatile("ld.shared.b32 %0, [%1];" : "=r"(a[mi][r]) : "r"(addr));
                        }
                    }
                    uint32_t b[4][2];
                    #pragma unroll
                    for (int ni = 0; ni < 4; ni++) {
                        int rowb = row_b + ni * 8 + (lane >> 2);
                        #pragma unroll
                        for (int r = 0; r < 2; r++) {
                            int u = kk * 2 + r;
                            uint32_t addr = Bs + rowb * 128 + ((u ^ (rowb & 7)) << 4) + ((lane & 3) << 2);
                            asm volatile("ld.shared.b32 %0, [%1];" : "=r"(b[ni][r]) : "r"(addr));
                        }
                    }
                    #pragma unroll
                    for (int mi = 0; mi < 4; mi++)
                        #pragma unroll
                        for (int ni = 0; ni < 4; ni++)
                            MMA_BF16(acc[mi][ni], a[mi], b[ni]);
                }
                __syncthreads();
                if (it + 2 < ITBF) load_stage(it + 2, s);
                CP_COMMIT();                        // unconditional (tail-correct)
            }

            float rs0[4], rs1[4];
            #pragma unroll
            for (int mi = 0; mi < 4; mi++) {
                int row0 = m0 + row_a + mi * 16 + (lane >> 2);
                rs0[mi] = g_rowscale[row0] * wsc;
                rs1[mi] = g_rowscale[row0 + 8] * wsc;
            }
            #pragma unroll
            for (int ni = 0; ni < 4; ni++) {
                int col = n0 + row_b + ni * 8 + ((lane & 3) << 1);
                float b0 = bias[col], b1 = bias[col + 1];
                #pragma unroll
                for (int mi = 0; mi < 4; mi++) {
                    int row0 = m0 + row_a + mi * 16 + (lane >> 2);
                    const float* cc = acc[mi][ni];
                    float2 v0 = make_float2(cc[0] * rs0[mi] + b0, cc[1] * rs0[mi] + b1);
                    float2 v1 = make_float2(cc[2] * rs1[mi] + b0, cc[3] * rs1[mi] + b1);
                    *reinterpret_cast<float2*>(out + (size_t)row0 * NN + col) = v0;
                    *reinterpret_cast<float2*>(out + (size_t)(row0 + 8) * NN + col) = v1;
                }
            }
        } else {
            // ---------------- s8 engine ----------------
            const int8_t* Ag = g_act8 + (size_t)m0 * KK;
            const int8_t* Bg = g_wq8 + (size_t)n0 * KK;
            int acc[4][4][4];
            #pragma unroll
            for (int i = 0; i < 4; i++)
                #pragma unroll
                for (int j = 0; j < 4; j++)
                    #pragma unroll
                    for (int k = 0; k < 4; k++) acc[i][j][k] = 0;

            auto load_stage = [&](int it, int s) {
                uint32_t As = sbase + s * STGB;
                uint32_t Bs = As + AST;
                #pragma unroll
                for (int i = 0; i < 4; i++) {
                    int cc = tid + i * 256;
                    int row = cc >> 3, u = cc & 7;
                    uint32_t so = row * 128 + ((u ^ (row & 7)) << 4);
                    CP_ASYNC16(As + so, Ag + (size_t)row * KK + it * SK8 + u * 16);
                    CP_ASYNC16(Bs + so, Bg + (size_t)row * KK + it * SK8 + u * 16);
                }
            };

            load_stage(0, 0); CP_COMMIT();
            load_stage(1, 1); CP_COMMIT();

            for (int it = 0; it < IT8; ++it) {
                int s = it & 1;
                CP_WAIT(1);
                __syncthreads();
                uint32_t As = sbase + s * STGB;
                uint32_t Bs = As + AST;
                #pragma unroll
                for (int kk = 0; kk < 4; ++kk) {    // 4 x K=32
                    uint32_t a[4][4];
                    #pragma unroll
                    for (int mi = 0; mi < 4; mi++) {
                        int row0 = row_a + mi * 16 + (lane >> 2);
                        #pragma unroll
                        for (int r = 0; r < 4; r++) {
                            int row = row0 + ((r & 1) << 3);
                            int u = kk * 2 + (r >> 1);
                            uint32_t addr = As + row * 128 + ((u ^ (row & 7)) << 4) + ((lane & 3) << 2);
                            asm volatile("ld.shared.b32 %0, [%1];" : "=r"(a[mi][r]) : "r"(addr));
                        }
                    }
                    uint32_t b[4][2];
                    #pragma unroll
                    for (int ni = 0; ni < 4; ni++) {
                        int rowb = row_b + ni * 8 + (lane >> 2);
                        #pragma unroll
                        for (int r = 0; r < 2; r++) {
                            int u = kk * 2 + r;
                            uint32_t addr = Bs + rowb * 128 + ((u ^ (rowb & 7)) << 4) + ((lane & 3) << 2);
                            asm volatile("ld.shared.b32 %0, [%1];" : "=r"(b[ni][r]) : "r"(addr));
                        }
                    }
                    #pragma unroll
                    for (int mi = 0; mi < 4; mi++)
                        #pragma unroll
                        for (int ni = 0; ni < 4; ni++)
                            MMA_S8(acc[mi][ni], a[mi], b[ni]);
                }
                __syncthreads();
                if (it + 2 < IT8) load_stage(it + 2, s);
                CP_COMMIT();                        // unconditional (tail-correct)
            }

            float rs0[4], rs1[4];
            #pragma unroll
            for (int mi = 0; mi < 4; mi++) {
                int row0 = m0 + row_a + mi * 16 + (lane >> 2);
                rs0[mi] = g_rowscale[row0] * wsc;
                rs1[mi] = g_rowscale[row0 + 8] * wsc;
            }
            #pragma unroll
            for (int ni = 0; ni < 4; ni++) {
                int col = n0 + row_b + ni * 8 + ((lane & 3) << 1);
                float b0 = bias[col], b1 = bias[col + 1];
                #pragma unroll
                for (int mi = 0; mi < 4; mi++) {
                    int row0 = m0 + row_a + mi * 16 + (lane >> 2);
                    const int* cc = acc[mi][ni];
                    float2 v0 = make_float2(__int2float_rn(cc[0]) * rs0[mi] + b0,
                                            __int2float_rn(cc[1]) * rs0[mi] + b1);
                    float2 v1 = make_float2(__int2float_rn(cc[2]) * rs1[mi] + b0,
                                            __int2float_rn(cc[3]) * rs1[mi] + b1);
                    *reinterpret_cast<float2*>(out + (size_t)row0 * NN + col) = v0;
                    *reinterpret_cast<float2*>(out + (size_t)(row0 + 8) * NN + col) = v1;
                }
            }
        }
        __syncthreads();    // protect s_tile rewrite + smem reuse next tile
    }
}

// ============================================================
// Host side — single stream (multi-stream forks cost ~38us in this
// harness's graph replay; measured twice).
// ============================================================
extern "C" void kernel_launch(void* const* d_in, const int* in_sizes, int n_in,
                              void* d_out, int out_size) {
    const float* x    = (const float*)d_in[0];
    const float* w    = (const float*)d_in[1];
    const float* bias = (const float*)d_in[2];
    float* out = (float*)d_out;

    static bool init = false;
    if (!init) {
        cudaFuncSetAttribute(gemm_pers_kernel, cudaFuncAttributeMaxDynamicSharedMemorySize, GEMM_SMEM);
        init = true;
    }

    // reset all scheduler/done counters (small, cheap, race-free)
    void* ctrp = nullptr;
    cudaGetSymbolAddress(&ctrp, g_ctr);
    cudaMemsetAsync(ctrp, 0, sizeof(unsigned) * 260, 0);

    wabs_kernel<<<NN, 256>>>(w);            // includes merged s_w finalization
    ternarize_kernel<<<(NN * KK / 4) / 256, 256>>>(w);
    ln_quant_kernel<<<MM, 128>>>(x);
    gemm_pers_kernel<<<NPERS, 256, GEMM_SMEM>>>(bias, out);
}

// round 15
// speedup vs baseline: 1.3691x; 1.3691x over previous
#include <cuda_runtime.h>
#include <cuda_bf16.h>
#include <cstdint>

// ============================================================
// Problem sizes (fixed by the dataset)
// ============================================================
static constexpr int MM = 16384;   // B*S tokens
static constexpr int KK = 2048;    // D_IN
static constexpr int NN = 2048;    // D_OUT

// -------- unified GEMM tiling: CTA tile 128x128, 128B rows --------
static constexpr int TM = 128;
static constexpr int TN = 128;
static constexpr int SK8  = 128;                 // int8 per stage row
static constexpr int SKBF = 64;                  // bf16 per stage row (same 128B)
static constexpr int IT8  = KK / SK8;            // 16
static constexpr int ITBF = KK / SKBF;           // 32
static constexpr int AST  = TM * 128;            // 16 KB
static constexpr int STGB = 2 * AST;             // 32 KB (A + B)
static constexpr int GEMM_SMEM = 2 * STGB;       // 64 KB (2 stages)

// tile pools: 2048 tiles of 128x128
static constexpr int N_BF = 1064;                // bf16 pool [0, N_BF)
static constexpr int N_S8 = 2048 - N_BF;         // s8 pool  [N_BF, 2048)
static constexpr int NPERS = 304;                // persistent CTAs (2 per SM)

// [0] = bf16 pool counter, [1] = s8 pool counter, [2+smid] = per-SM arrival
__device__ unsigned g_ctr[260];

// ============================================================
// Device scratch (static — no allocation allowed)
// ============================================================
__device__ __align__(1024) int8_t g_act8[(size_t)MM * KK];            // 32 MB
__device__ __align__(1024) int8_t g_wq8[(size_t)NN * KK];             //  4 MB
__device__ __align__(1024) __nv_bfloat16 g_actbf[(size_t)MM * KK];    // 64 MB
__device__ __align__(1024) __nv_bfloat16 g_wqbf[(size_t)NN * KK];     //  8 MB
__device__ float g_rowscale[MM];
__device__ float g_wpart[NN];
__device__ float g_wscale;   // = max(mean|W|, eps) = 1/s_w
__device__ float g_sw;       // = s_w

// ============================================================
// PTX helpers
// ============================================================
__device__ __forceinline__ uint32_t smem_u32(const void* p) {
    uint32_t a;
    asm("{ .reg .u64 t; cvta.to.shared.u64 t, %1; cvt.u32.u64 %0, t; }" : "=r"(a) : "l"(p));
    return a;
}

#define CP_ASYNC16(smem_addr, gmem_ptr) \
    asm volatile("cp.async.cg.shared.global [%0], [%1], 16;" \
        :: "r"(smem_addr), "l"(gmem_ptr) : "memory")
#define CP_COMMIT() asm volatile("cp.async.commit_group;" ::: "memory")
#define CP_WAIT(n)  asm volatile("cp.async.wait_group %0;" :: "n"(n) : "memory")

#define MMA_S8(c, a, b) \
    asm volatile( \
        "mma.sync.aligned.m16n8k32.row.col.s32.s8.s8.s32 " \
        "{%0,%1,%2,%3}, {%4,%5,%6,%7}, {%8,%9}, {%0,%1,%2,%3};" \
        : "+r"((c)[0]), "+r"((c)[1]), "+r"((c)[2]), "+r"((c)[3]) \
        : "r"((a)[0]), "r"((a)[1]), "r"((a)[2]), "r"((a)[3]), \
          "r"((b)[0]), "r"((b)[1]))

#define MMA_BF16(c, a, b) \
    asm volatile( \
        "mma.sync.aligned.m16n8k16.row.col.f32.bf16.bf16.f32 " \
        "{%0,%1,%2,%3}, {%4,%5,%6,%7}, {%8,%9}, {%0,%1,%2,%3};" \
        : "+f"((c)[0]), "+f"((c)[1]), "+f"((c)[2]), "+f"((c)[3]) \
        : "r"((a)[0]), "r"((a)[1]), "r"((a)[2]), "r"((a)[3]), \
          "r"((b)[0]), "r"((b)[1]))

__device__ __forceinline__ uint32_t pack4_s8(float q0, float q1, float q2, float q3) {
    int i0 = (int)q0, i1 = (int)q1, i2 = (int)q2, i3 = (int)q3;
    return (uint32_t)(i0 & 255) | ((uint32_t)(i1 & 255) << 8) |
           ((uint32_t)(i2 & 255) << 16) | ((uint32_t)(i3 & 255) << 24);
}

__device__ __forceinline__ float warp_sum(float v) {
    #pragma unroll
    for (int o = 16; o > 0; o >>= 1) v += __shfl_xor_sync(0xFFFFFFFFu, v, o);
    return v;
}
__device__ __forceinline__ float warp_max(float v) {
    #pragma unroll
    for (int o = 16; o > 0; o >>= 1) v = fmaxf(v, __shfl_xor_sync(0xFFFFFFFFu, v, o));
    return v;
}

// ============================================================
// Kernel 1: per-row |W| sums (deterministic)
// ============================================================
__global__ void __launch_bounds__(256) wabs_kernel(const float* __restrict__ w) {
    __shared__ float red[8];
    int row = blockIdx.x, t = threadIdx.x, lane = t & 31, wi = t >> 5;
    const float4* wr = reinterpret_cast<const float4*>(w) + (size_t)row * (KK / 4);
    float4 a = wr[t], b = wr[256 + t];
    float s = fabsf(a.x) + fabsf(a.y) + fabsf(a.z) + fabsf(a.w)
            + fabsf(b.x) + fabsf(b.y) + fabsf(b.z) + fabsf(b.w);
    s = warp_sum(s);
    if (lane == 0) red[wi] = s;
    __syncthreads();
    if (t == 0) {
        float tot = 0.f;
        #pragma unroll
        for (int i = 0; i < 8; i++) tot += red[i];
        g_wpart[row] = tot;
    }
}

// Kernel 2: finalize s_w
__global__ void __launch_bounds__(256) wfinal_kernel() {
    __shared__ float red[8];
    int t = threadIdx.x, lane = t & 31, wi = t >> 5;
    float s = 0.f;
    #pragma unroll
    for (int i = 0; i < NN / 256; i++) s += g_wpart[t + i * 256];
    s = warp_sum(s);
    if (lane == 0) red[wi] = s;
    __syncthreads();
    if (t == 0) {
        float tot = 0.f;
        #pragma unroll
        for (int i = 0; i < 8; i++) tot += red[i];
        float mean = tot * (1.0f / ((float)NN * (float)KK));
        float ws = fmaxf(mean, 1e-8f);
        g_wscale = ws;         // 1/s_w
        g_sw = 1.0f / ws;      // s_w
    }
}

// Kernel 3: ternarize weight -> int8 {-1,0,1} AND bf16 copies
__global__ void __launch_bounds__(256) ternarize_kernel(const float* __restrict__ w) {
    int i = blockIdx.x * 256 + threadIdx.x;   // float4 index, total NN*KK/4
    float sw = g_sw;
    float4 v = reinterpret_cast<const float4*>(w)[i];
    float t0 = fminf(fmaxf(rintf(sw * v.x), -1.f), 1.f);
    float t1 = fminf(fmaxf(rintf(sw * v.y), -1.f), 1.f);
    float t2 = fminf(fmaxf(rintf(sw * v.z), -1.f), 1.f);
    float t3 = fminf(fmaxf(rintf(sw * v.w), -1.f), 1.f);
    reinterpret_cast<uint32_t*>(g_wq8)[i] = pack4_s8(t0, t1, t2, t3);
    __nv_bfloat162 p0, p1;
    p0.x = __float2bfloat16(t0); p0.y = __float2bfloat16(t1);
    p1.x = __float2bfloat16(t2); p1.y = __float2bfloat16(t3);
    __nv_bfloat162* dst = reinterpret_cast<__nv_bfloat162*>(g_wqbf);
    dst[2 * i]     = p0;
    dst[2 * i + 1] = p1;
}

// ============================================================
// Kernel 4: LayerNorm + per-token int8 fake-quant -> int8 + bf16 + row scale
// ============================================================
__global__ void __launch_bounds__(128) ln_quant_kernel(const float* __restrict__ x) {
    __shared__ float ssum[4], ssq[4], smx[4];
    int row = blockIdx.x, t = threadIdx.x, lane = t & 31, wi = t >> 5;
    const float4* xr = reinterpret_cast<const float4*>(x) + (size_t)row * (KK / 4);
    float4 v[4];
    #pragma unroll
    for (int i = 0; i < 4; i++) v[i] = xr[t + 128 * i];

    float s = 0.f;
    #pragma unroll
    for (int i = 0; i < 4; i++) s += v[i].x + v[i].y + v[i].z + v[i].w;
    s = warp_sum(s);
    if (lane == 0) ssum[wi] = s;
    __syncthreads();
    float mu = (ssum[0] + ssum[1] + ssum[2] + ssum[3]) * (1.0f / (float)KK);

    float d[16];
    #pragma unroll
    for (int i = 0; i < 4; i++) {
        d[4*i+0] = v[i].x - mu; d[4*i+1] = v[i].y - mu;
        d[4*i+2] = v[i].z - mu; d[4*i+3] = v[i].w - mu;
    }
    float sq = 0.f, mx = 0.f;
    #pragma unroll
    for (int i = 0; i < 16; i++) { sq += d[i] * d[i]; mx = fmaxf(mx, fabsf(d[i])); }
    sq = warp_sum(sq); mx = warp_max(mx);
    if (lane == 0) { ssq[wi] = sq; smx[wi] = mx; }
    __syncthreads();
    float var = (ssq[0] + ssq[1] + ssq[2] + ssq[3]) * (1.0f / (float)KK);
    float r = 1.0f / sqrtf(var + 1e-8f);
    float amax = fmaxf(r * fmaxf(fmaxf(smx[0], smx[1]), fmaxf(smx[2], smx[3])), 1e-8f);
    float sact = 127.0f / amax;
    if (t == 0) g_rowscale[row] = (amax * (1.0f / 127.0f)) * g_wscale;

    float sr = sact * r;
    uint32_t* arow = reinterpret_cast<uint32_t*>(g_act8 + (size_t)row * KK);
    __nv_bfloat162* brow = reinterpret_cast<__nv_bfloat162*>(g_actbf + (size_t)row * KK);
    #pragma unroll
    for (int i = 0; i < 4; i++) {
        float q0 = fminf(fmaxf(rintf(sr * d[4*i+0]), -128.f), 127.f);
        float q1 = fminf(fmaxf(rintf(sr * d[4*i+1]), -128.f), 127.f);
        float q2 = fminf(fmaxf(rintf(sr * d[4*i+2]), -128.f), 127.f);
        float q3 = fminf(fmaxf(rintf(sr * d[4*i+3]), -128.f), 127.f);
        int idx = t + 128 * i;
        arow[idx] = pack4_s8(q0, q1, q2, q3);
        __nv_bfloat162 p0, p1;
        p0.x = __float2bfloat16(q0); p0.y = __float2bfloat16(q1);
        p1.x = __float2bfloat16(q2); p1.y = __float2bfloat16(q3);
        brow[2 * idx]     = p0;
        brow[2 * idx + 1] = p1;
    }
}

// ============================================================
// Kernel 5: persistent dual-engine GEMM.
// Each SM hosts exactly one s8 CTA + one bf16 CTA for the whole GEMM
// (type = per-SM arrival index & 1, via %smid). Tiles come from two
// atomic pools with cross-type stealing at the tail. Both engines
// produce bit-identical integer-exact results for any tile.
// ============================================================
__global__ void __launch_bounds__(256, 2)
gemm_pers_kernel(const float* __restrict__ bias, float* __restrict__ out) {
    extern __shared__ __align__(128) char smem[];
    const uint32_t sbase = smem_u32(smem);
    const int tid = threadIdx.x, lane = tid & 31, wid = tid >> 5;
    const int wm = wid >> 2, wn = wid & 3;         // warp grid 2x4, warp tile 64x32
    __shared__ int s_type, s_tile;

    if (tid == 0) {
        uint32_t smid;
        asm("mov.u32 %0, %%smid;" : "=r"(smid));
        unsigned idx = atomicAdd(&g_ctr[2 + smid], 1u);
        s_type = (int)(idx & 1u);                  // 0 = bf16, 1 = s8
    }
    __syncthreads();
    const int type = s_type;

    const int row_a = wm * 64;
    const int row_b = wn * 32;

    for (;;) {
        if (tid == 0) {
            int tile = -1;
            if (type == 0) {
                unsigned t = atomicAdd(&g_ctr[0], 1u);
                if (t < N_BF) tile = (int)t;
                else {
                    unsigned u = atomicAdd(&g_ctr[1], 1u);
                    if (u < N_S8) tile = N_BF + (int)u;
                }
            } else {
                unsigned t = atomicAdd(&g_ctr[1], 1u);
                if (t < N_S8) tile = N_BF + (int)t;
                else {
                    unsigned u = atomicAdd(&g_ctr[0], 1u);
                    if (u < N_BF) tile = (int)u;
                }
            }
            s_tile = tile;
        }
        __syncthreads();
        const int tile = s_tile;
        if (tile < 0) break;
        const int m0 = (tile >> 4) * TM;
        const int n0 = (tile & 15) * TN;

        if (type == 0) {
            // ---------------- bf16 engine ----------------
            const __nv_bfloat16* Ag = g_actbf + (size_t)m0 * KK;
            const __nv_bfloat16* Bg = g_wqbf + (size_t)n0 * KK;
            float acc[4][4][4];
            #pragma unroll
            for (int i = 0; i < 4; i++)
                #pragma unroll
                for (int j = 0; j < 4; j++)
                    #pragma unroll
                    for (int k = 0; k < 4; k++) acc[i][j][k] = 0.f;

            auto load_stage = [&](int it, int s) {
                uint32_t As = sbase + s * STGB;
                uint32_t Bs = As + AST;
                #pragma unroll
                for (int i = 0; i < 4; i++) {
                    int cc = tid + i * 256;
                    int row = cc >> 3, u = cc & 7;
                    uint32_t so = row * 128 + ((u ^ (row & 7)) << 4);
                    CP_ASYNC16(As + so, Ag + (size_t)row * KK + it * SKBF + u * 8);
                    CP_ASYNC16(Bs + so, Bg + (size_t)row * KK + it * SKBF + u * 8);
                }
            };

            load_stage(0, 0); CP_COMMIT();
            load_stage(1, 1); CP_COMMIT();

            for (int it = 0; it < ITBF; ++it) {
                int s = it & 1;
                CP_WAIT(1);
                __syncthreads();
                uint32_t As = sbase + s * STGB;
                uint32_t Bs = As + AST;
                #pragma unroll
                for (int kk = 0; kk < 4; ++kk) {    // 4 x K=16
                    uint32_t a[4][4];
                    #pragma unroll
                    for (int mi = 0; mi < 4; mi++) {
                        int row0 = row_a + mi * 16 + (lane >> 2);
                        #pragma unroll
                        for (int r = 0; r < 4; r++) {
                            int row = row0 + ((r & 1) << 3);
                            int u = kk * 2 + (r >> 1);
                            uint32_t addr = As + row * 128 + ((u ^ (row & 7)) << 4) + ((lane & 3) << 2);
                            asm volatile("ld.shared.b32 %0, [%1];" : "=r"(a[mi][r]) : "r"(addr));
                        }
                    }
                    uint32_t b[4][2];
                    #pragma unroll
                    for (int ni = 0; ni < 4; ni++) {
                        int rowb = row_b + ni * 8 + (lane >> 2);
                        #pragma unroll
                        for (int r = 0; r < 2; r++) {
                            int u = kk * 2 + r;
                            uint32_t addr = Bs + rowb * 128 + ((u ^ (rowb & 7)) << 4) + ((lane & 3) << 2);
                            asm volatile("ld.shared.b32 %0, [%1];" : "=r"(b[ni][r]) : "r"(addr));
                        }
                    }
                    #pragma unroll
                    for (int mi = 0; mi < 4; mi++)
                        #pragma unroll
                        for (int ni = 0; ni < 4; ni++)
                            MMA_BF16(acc[mi][ni], a[mi], b[ni]);
                }
                __syncthreads();
                if (it + 2 < ITBF) load_stage(it + 2, s);
                CP_COMMIT();                        // unconditional (tail-correct)
            }

            float rs0[4], rs1[4];
            #pragma unroll
            for (int mi = 0; mi < 4; mi++) {
                int row0 = m0 + row_a + mi * 16 + (lane >> 2);
                rs0[mi] = g_rowscale[row0];
                rs1[mi] = g_rowscale[row0 + 8];
            }
            #pragma unroll
            for (int ni = 0; ni < 4; ni++) {
                int col = n0 + row_b + ni * 8 + ((lane & 3) << 1);
                float b0 = bias[col], b1 = bias[col + 1];
                #pragma unroll
                for (int mi = 0; mi < 4; mi++) {
                    int row0 = m0 + row_a + mi * 16 + (lane >> 2);
                    const float* cc = acc[mi][ni];
                    float2 v0 = make_float2(cc[0] * rs0[mi] + b0, cc[1] * rs0[mi] + b1);
                    float2 v1 = make_float2(cc[2] * rs1[mi] + b0, cc[3] * rs1[mi] + b1);
                    *reinterpret_cast<float2*>(out + (size_t)row0 * NN + col) = v0;
                    *reinterpret_cast<float2*>(out + (size_t)(row0 + 8) * NN + col) = v1;
                }
            }
        } else {
            // ---------------- s8 engine ----------------
            const int8_t* Ag = g_act8 + (size_t)m0 * KK;
            const int8_t* Bg = g_wq8 + (size_t)n0 * KK;
            int acc[4][4][4];
            #pragma unroll
            for (int i = 0; i < 4; i++)
                #pragma unroll
                for (int j = 0; j < 4; j++)
                    #pragma unroll
                    for (int k = 0; k < 4; k++) acc[i][j][k] = 0;

            auto load_stage = [&](int it, int s) {
                uint32_t As = sbase + s * STGB;
                uint32_t Bs = As + AST;
                #pragma unroll
                for (int i = 0; i < 4; i++) {
                    int cc = tid + i * 256;
                    int row = cc >> 3, u = cc & 7;
                    uint32_t so = row * 128 + ((u ^ (row & 7)) << 4);
                    CP_ASYNC16(As + so, Ag + (size_t)row * KK + it * SK8 + u * 16);
                    CP_ASYNC16(Bs + so, Bg + (size_t)row * KK + it * SK8 + u * 16);
                }
            };

            load_stage(0, 0); CP_COMMIT();
            load_stage(1, 1); CP_COMMIT();

            for (int it = 0; it < IT8; ++it) {
                int s = it & 1;
                CP_WAIT(1);
                __syncthreads();
                uint32_t As = sbase + s * STGB;
                uint32_t Bs = As + AST;
                #pragma unroll
                for (int kk = 0; kk < 4; ++kk) {    // 4 x K=32
                    uint32_t a[4][4];
                    #pragma unroll
                    for (int mi = 0; mi < 4; mi++) {
                        int row0 = row_a + mi * 16 + (lane >> 2);
                        #pragma unroll
                        for (int r = 0; r < 4; r++) {
                            int row = row0 + ((r & 1) << 3);
                            int u = kk * 2 + (r >> 1);
                            uint32_t addr = As + row * 128 + ((u ^ (row & 7)) << 4) + ((lane & 3) << 2);
                            asm volatile("ld.shared.b32 %0, [%1];" : "=r"(a[mi][r]) : "r"(addr));
                        }
                    }
                    uint32_t b[4][2];
                    #pragma unroll
                    for (int ni = 0; ni < 4; ni++) {
                        int rowb = row_b + ni * 8 + (lane >> 2);
                        #pragma unroll
                        for (int r = 0; r < 2; r++) {
                            int u = kk * 2 + r;
                            uint32_t addr = Bs + rowb * 128 + ((u ^ (rowb & 7)) << 4) + ((lane & 3) << 2);
                            asm volatile("ld.shared.b32 %0, [%1];" : "=r"(b[ni][r]) : "r"(addr));
                        }
                    }
                    #pragma unroll
                    for (int mi = 0; mi < 4; mi++)
                        #pragma unroll
                        for (int ni = 0; ni < 4; ni++)
                            MMA_S8(acc[mi][ni], a[mi], b[ni]);
                }
                __syncthreads();
                if (it + 2 < IT8) load_stage(it + 2, s);
                CP_COMMIT();                        // unconditional (tail-correct)
            }

            float rs0[4], rs1[4];
            #pragma unroll
            for (int mi = 0; mi < 4; mi++) {
                int row0 = m0 + row_a + mi * 16 + (lane >> 2);
                rs0[mi] = g_rowscale[row0];
                rs1[mi] = g_rowscale[row0 + 8];
            }
            #pragma unroll
            for (int ni = 0; ni < 4; ni++) {
                int col = n0 + row_b + ni * 8 + ((lane & 3) << 1);
                float b0 = bias[col], b1 = bias[col + 1];
                #pragma unroll
                for (int mi = 0; mi < 4; mi++) {
                    int row0 = m0 + row_a + mi * 16 + (lane >> 2);
                    const int* cc = acc[mi][ni];
                    float2 v0 = make_float2(__int2float_rn(cc[0]) * rs0[mi] + b0,
                                            __int2float_rn(cc[1]) * rs0[mi] + b1);
                    float2 v1 = make_float2(__int2float_rn(cc[2]) * rs1[mi] + b0,
                                            __int2float_rn(cc[3]) * rs1[mi] + b1);
                    *reinterpret_cast<float2*>(out + (size_t)row0 * NN + col) = v0;
                    *reinterpret_cast<float2*>(out + (size_t)(row0 + 8) * NN + col) = v1;
                }
            }
        }
        __syncthreads();    // protect s_tile rewrite + smem reuse next tile
    }
}

// ============================================================
// Host side
// ============================================================
extern "C" void kernel_launch(void* const* d_in, const int* in_sizes, int n_in,
                              void* d_out, int out_size) {
    const float* x    = (const float*)d_in[0];
    const float* w    = (const float*)d_in[1];
    const float* bias = (const float*)d_in[2];
    float* out = (float*)d_out;

    // reset tile-pool + per-SM pairing counters (graph-capturable memset)
    void* ctrp = nullptr;
    cudaGetSymbolAddress(&ctrp, g_ctr);
    cudaMemsetAsync(ctrp, 0, sizeof(unsigned) * 260, 0);

    wabs_kernel<<<NN, 256>>>(w);
    wfinal_kernel<<<1, 256>>>();
    ternarize_kernel<<<(NN * KK / 4) / 256, 256>>>(w);
    ln_quant_kernel<<<MM, 128>>>(x);

    static bool attr_set = false;
    if (!attr_set) {
        cudaFuncSetAttribute(gemm_pers_kernel, cudaFuncAttributeMaxDynamicSharedMemorySize, GEMM_SMEM);
        attr_set = true;
    }
    gemm_pers_kernel<<<NPERS, 256, GEMM_SMEM>>>(bias, out);
}

// round 16
// speedup vs baseline: 1.5153x; 1.1068x over previous
#include <cuda_runtime.h>
#include <cuda_bf16.h>
#include <cstdint>

// ============================================================
// Problem sizes (fixed by the dataset)
// ============================================================
static constexpr int MM = 16384;   // B*S tokens
static constexpr int KK = 2048;    // D_IN
static constexpr int NN = 2048;    // D_OUT

// -------- unified GEMM tiling: CTA tile 128x128, 128B rows --------
static constexpr int TM = 128;
static constexpr int TN = 128;
static constexpr int SK8  = 128;                 // int8 per stage row
static constexpr int SKBF = 64;                  // bf16 per stage row (same 128B)
static constexpr int IT8  = KK / SK8;            // 16
static constexpr int ITBF = KK / SKBF;           // 32
static constexpr int AST  = TM * 128;            // 16 KB
static constexpr int STGB = 2 * AST;             // 32 KB (A + B)
static constexpr int GEMM_SMEM = 3 * STGB;       // 96 KB (3-buffer ring, 1 barrier/iter)

// tile pools: 2048 tiles of 128x128
static constexpr int N_BF = 1064;                // bf16 pool [0, N_BF)
static constexpr int N_S8 = 2048 - N_BF;         // s8 pool  [N_BF, 2048)
static constexpr int NPERS = 304;                // persistent CTAs (2 per SM)

// [0] = bf16 pool counter, [1] = s8 pool counter, [2+smid] = per-SM arrival
__device__ unsigned g_ctr[260];

// ============================================================
// Device scratch (static — no allocation allowed)
// ============================================================
__device__ __align__(1024) int8_t g_act8[(size_t)MM * KK];            // 32 MB
__device__ __align__(1024) int8_t g_wq8[(size_t)NN * KK];             //  4 MB
__device__ __align__(1024) __nv_bfloat16 g_actbf[(size_t)MM * KK];    // 64 MB
__device__ __align__(1024) __nv_bfloat16 g_wqbf[(size_t)NN * KK];     //  8 MB
__device__ float g_rowscale[MM];
__device__ float g_wpart[NN];
__device__ float g_wscale;   // = max(mean|W|, eps) = 1/s_w
__device__ float g_sw;       // = s_w

// ============================================================
// PTX helpers
// ============================================================
__device__ __forceinline__ uint32_t smem_u32(const void* p) {
    uint32_t a;
    asm("{ .reg .u64 t; cvta.to.shared.u64 t, %1; cvt.u32.u64 %0, t; }" : "=r"(a) : "l"(p));
    return a;
}

#define CP_ASYNC16(smem_addr, gmem_ptr) \
    asm volatile("cp.async.cg.shared.global [%0], [%1], 16;" \
        :: "r"(smem_addr), "l"(gmem_ptr) : "memory")
#define CP_COMMIT() asm volatile("cp.async.commit_group;" ::: "memory")
#define CP_WAIT(n)  asm volatile("cp.async.wait_group %0;" :: "n"(n) : "memory")

#define MMA_S8(c, a, b) \
    asm volatile( \
        "mma.sync.aligned.m16n8k32.row.col.s32.s8.s8.s32 " \
        "{%0,%1,%2,%3}, {%4,%5,%6,%7}, {%8,%9}, {%0,%1,%2,%3};" \
        : "+r"((c)[0]), "+r"((c)[1]), "+r"((c)[2]), "+r"((c)[3]) \
        : "r"((a)[0]), "r"((a)[1]), "r"((a)[2]), "r"((a)[3]), \
          "r"((b)[0]), "r"((b)[1]))

#define MMA_BF16(c, a, b) \
    asm volatile( \
        "mma.sync.aligned.m16n8k16.row.col.f32.bf16.bf16.f32 " \
        "{%0,%1,%2,%3}, {%4,%5,%6,%7}, {%8,%9}, {%0,%1,%2,%3};" \
        : "+f"((c)[0]), "+f"((c)[1]), "+f"((c)[2]), "+f"((c)[3]) \
        : "r"((a)[0]), "r"((a)[1]), "r"((a)[2]), "r"((a)[3]), \
          "r"((b)[0]), "r"((b)[1]))

__device__ __forceinline__ uint32_t pack4_s8(float q0, float q1, float q2, float q3) {
    int i0 = (int)q0, i1 = (int)q1, i2 = (int)q2, i3 = (int)q3;
    return (uint32_t)(i0 & 255) | ((uint32_t)(i1 & 255) << 8) |
           ((uint32_t)(i2 & 255) << 16) | ((uint32_t)(i3 & 255) << 24);
}

__device__ __forceinline__ float warp_sum(float v) {
    #pragma unroll
    for (int o = 16; o > 0; o >>= 1) v += __shfl_xor_sync(0xFFFFFFFFu, v, o);
    return v;
}
__device__ __forceinline__ float warp_max(float v) {
    #pragma unroll
    for (int o = 16; o > 0; o >>= 1) v = fmaxf(v, __shfl_xor_sync(0xFFFFFFFFu, v, o));
    return v;
}

// ============================================================
// Kernel 1: per-row |W| sums (deterministic)
// ============================================================
__global__ void __launch_bounds__(256) wabs_kernel(const float* __restrict__ w) {
    __shared__ float red[8];
    int row = blockIdx.x, t = threadIdx.x, lane = t & 31, wi = t >> 5;
    const float4* wr = reinterpret_cast<const float4*>(w) + (size_t)row * (KK / 4);
    float4 a = wr[t], b = wr[256 + t];
    float s = fabsf(a.x) + fabsf(a.y) + fabsf(a.z) + fabsf(a.w)
            + fabsf(b.x) + fabsf(b.y) + fabsf(b.z) + fabsf(b.w);
    s = warp_sum(s);
    if (lane == 0) red[wi] = s;
    __syncthreads();
    if (t == 0) {
        float tot = 0.f;
        #pragma unroll
        for (int i = 0; i < 8; i++) tot += red[i];
        g_wpart[row] = tot;
    }
}

// Kernel 2: finalize s_w
__global__ void __launch_bounds__(256) wfinal_kernel() {
    __shared__ float red[8];
    int t = threadIdx.x, lane = t & 31, wi = t >> 5;
    float s = 0.f;
    #pragma unroll
    for (int i = 0; i < NN / 256; i++) s += g_wpart[t + i * 256];
    s = warp_sum(s);
    if (lane == 0) red[wi] = s;
    __syncthreads();
    if (t == 0) {
        float tot = 0.f;
        #pragma unroll
        for (int i = 0; i < 8; i++) tot += red[i];
        float mean = tot * (1.0f / ((float)NN * (float)KK));
        float ws = fmaxf(mean, 1e-8f);
        g_wscale = ws;         // 1/s_w
        g_sw = 1.0f / ws;      // s_w
    }
}

// Kernel 3: ternarize weight -> int8 {-1,0,1} AND bf16 copies
__global__ void __launch_bounds__(256) ternarize_kernel(const float* __restrict__ w) {
    int i = blockIdx.x * 256 + threadIdx.x;   // float4 index, total NN*KK/4
    float sw = g_sw;
    float4 v = reinterpret_cast<const float4*>(w)[i];
    float t0 = fminf(fmaxf(rintf(sw * v.x), -1.f), 1.f);
    float t1 = fminf(fmaxf(rintf(sw * v.y), -1.f), 1.f);
    float t2 = fminf(fmaxf(rintf(sw * v.z), -1.f), 1.f);
    float t3 = fminf(fmaxf(rintf(sw * v.w), -1.f), 1.f);
    reinterpret_cast<uint32_t*>(g_wq8)[i] = pack4_s8(t0, t1, t2, t3);
    __nv_bfloat162 p0, p1;
    p0.x = __float2bfloat16(t0); p0.y = __float2bfloat16(t1);
    p1.x = __float2bfloat16(t2); p1.y = __float2bfloat16(t3);
    __nv_bfloat162* dst = reinterpret_cast<__nv_bfloat162*>(g_wqbf);
    dst[2 * i]     = p0;
    dst[2 * i + 1] = p1;
}

// ============================================================
// Kernel 4: LayerNorm + per-token int8 fake-quant -> int8 + bf16 + row scale
// ============================================================
__global__ void __launch_bounds__(128) ln_quant_kernel(const float* __restrict__ x) {
    __shared__ float ssum[4], ssq[4], smx[4];
    int row = blockIdx.x, t = threadIdx.x, lane = t & 31, wi = t >> 5;
    const float4* xr = reinterpret_cast<const float4*>(x) + (size_t)row * (KK / 4);
    float4 v[4];
    #pragma unroll
    for (int i = 0; i < 4; i++) v[i] = xr[t + 128 * i];

    float s = 0.f;
    #pragma unroll
    for (int i = 0; i < 4; i++) s += v[i].x + v[i].y + v[i].z + v[i].w;
    s = warp_sum(s);
    if (lane == 0) ssum[wi] = s;
    __syncthreads();
    float mu = (ssum[0] + ssum[1] + ssum[2] + ssum[3]) * (1.0f / (float)KK);

    float d[16];
    #pragma unroll
    for (int i = 0; i < 4; i++) {
        d[4*i+0] = v[i].x - mu; d[4*i+1] = v[i].y - mu;
        d[4*i+2] = v[i].z - mu; d[4*i+3] = v[i].w - mu;
    }
    float sq = 0.f, mx = 0.f;
    #pragma unroll
    for (int i = 0; i < 16; i++) { sq += d[i] * d[i]; mx = fmaxf(mx, fabsf(d[i])); }
    sq = warp_sum(sq); mx = warp_max(mx);
    if (lane == 0) { ssq[wi] = sq; smx[wi] = mx; }
    __syncthreads();
    float var = (ssq[0] + ssq[1] + ssq[2] + ssq[3]) * (1.0f / (float)KK);
    float r = 1.0f / sqrtf(var + 1e-8f);
    float amax = fmaxf(r * fmaxf(fmaxf(smx[0], smx[1]), fmaxf(smx[2], smx[3])), 1e-8f);
    float sact = 127.0f / amax;
    if (t == 0) g_rowscale[row] = (amax * (1.0f / 127.0f)) * g_wscale;

    float sr = sact * r;
    uint32_t* arow = reinterpret_cast<uint32_t*>(g_act8 + (size_t)row * KK);
    __nv_bfloat162* brow = reinterpret_cast<__nv_bfloat162*>(g_actbf + (size_t)row * KK);
    #pragma unroll
    for (int i = 0; i < 4; i++) {
        float q0 = fminf(fmaxf(rintf(sr * d[4*i+0]), -128.f), 127.f);
        float q1 = fminf(fmaxf(rintf(sr * d[4*i+1]), -128.f), 127.f);
        float q2 = fminf(fmaxf(rintf(sr * d[4*i+2]), -128.f), 127.f);
        float q3 = fminf(fmaxf(rintf(sr * d[4*i+3]), -128.f), 127.f);
        int idx = t + 128 * i;
        arow[idx] = pack4_s8(q0, q1, q2, q3);
        __nv_bfloat162 p0, p1;
        p0.x = __float2bfloat16(q0); p0.y = __float2bfloat16(q1);
        p1.x = __float2bfloat16(q2); p1.y = __float2bfloat16(q3);
        brow[2 * idx]     = p0;
        brow[2 * idx + 1] = p1;
    }
}

// ============================================================
// Kernel 5: persistent dual-engine GEMM.
// 3-buffer ring, prefetch distance 2, ONE __syncthreads per iteration:
// iteration it reads stage it%3 and loads it+2 into (it+2)%3 — a buffer
// nobody reads this or next iteration; the top barrier of it+1 orders
// the reuse at it+3. Halves the barrier count vs the 2-stage loop.
// ============================================================
__global__ void __launch_bounds__(256, 2)
gemm_pers_kernel(const float* __restrict__ bias, float* __restrict__ out) {
    extern __shared__ __align__(128) char smem[];
    const uint32_t sbase = smem_u32(smem);
    const int tid = threadIdx.x, lane = tid & 31, wid = tid >> 5;
    const int wm = wid >> 2, wn = wid & 3;         // warp grid 2x4, warp tile 64x32
    __shared__ int s_type, s_tile;

    if (tid == 0) {
        uint32_t smid;
        asm("mov.u32 %0, %%smid;" : "=r"(smid));
        unsigned idx = atomicAdd(&g_ctr[2 + smid], 1u);
        s_type = (int)(idx & 1u);                  // 0 = bf16, 1 = s8
    }
    __syncthreads();
    const int type = s_type;

    const int row_a = wm * 64;
    const int row_b = wn * 32;

    for (;;) {
        if (tid == 0) {
            int tile = -1;
            if (type == 0) {
                unsigned t = atomicAdd(&g_ctr[0], 1u);
                if (t < N_BF) tile = (int)t;
                else {
                    unsigned u = atomicAdd(&g_ctr[1], 1u);
                    if (u < N_S8) tile = N_BF + (int)u;
                }
            } else {
                unsigned t = atomicAdd(&g_ctr[1], 1u);
                if (t < N_S8) tile = N_BF + (int)t;
                else {
                    unsigned u = atomicAdd(&g_ctr[0], 1u);
                    if (u < N_BF) tile = (int)u;
                }
            }
            s_tile = tile;
        }
        __syncthreads();
        const int tile = s_tile;
        if (tile < 0) break;
        const int m0 = (tile >> 4) * TM;
        const int n0 = (tile & 15) * TN;

        if (type == 0) {
            // ---------------- bf16 engine ----------------
            const __nv_bfloat16* Ag = g_actbf + (size_t)m0 * KK;
            const __nv_bfloat16* Bg = g_wqbf + (size_t)n0 * KK;
            float acc[4][4][4];
            #pragma unroll
            for (int i = 0; i < 4; i++)
                #pragma unroll
                for (int j = 0; j < 4; j++)
                    #pragma unroll
                    for (int k = 0; k < 4; k++) acc[i][j][k] = 0.f;

            auto load_stage = [&](int it, int s) {
                uint32_t As = sbase + s * STGB;
                uint32_t Bs = As + AST;
                #pragma unroll
                for (int i = 0; i < 4; i++) {
                    int cc = tid + i * 256;
                    int row = cc >> 3, u = cc & 7;
                    uint32_t so = row * 128 + ((u ^ (row & 7)) << 4);
                    CP_ASYNC16(As + so, Ag + (size_t)row * KK + it * SKBF + u * 8);
                    CP_ASYNC16(Bs + so, Bg + (size_t)row * KK + it * SKBF + u * 8);
                }
            };

            load_stage(0, 0); CP_COMMIT();
            load_stage(1, 1); CP_COMMIT();

            int st = 0;
            for (int it = 0; it < ITBF; ++it) {
                CP_WAIT(1);
                __syncthreads();                    // single barrier per iteration
                uint32_t As = sbase + st * STGB;
                uint32_t Bs = As + AST;
                #pragma unroll
                for (int kk = 0; kk < 4; ++kk) {    // 4 x K=16
                    uint32_t a[4][4];
                    #pragma unroll
                    for (int mi = 0; mi < 4; mi++) {
                        int row0 = row_a + mi * 16 + (lane >> 2);
                        #pragma unroll
                        for (int r = 0; r < 4; r++) {
                            int row = row0 + ((r & 1) << 3);
                            int u = kk * 2 + (r >> 1);
                            uint32_t addr = As + row * 128 + ((u ^ (row & 7)) << 4) + ((lane & 3) << 2);
                            asm volatile("ld.shared.b32 %0, [%1];" : "=r"(a[mi][r]) : "r"(addr));
                        }
                    }
                    uint32_t b[4][2];
                    #pragma unroll
                    for (int ni = 0; ni < 4; ni++) {
                        int rowb = row_b + ni * 8 + (lane >> 2);
                        #pragma unroll
                        for (int r = 0; r < 2; r++) {
                            int u = kk * 2 + r;
                            uint32_t addr = Bs + rowb * 128 + ((u ^ (rowb & 7)) << 4) + ((lane & 3) << 2);
                            asm volatile("ld.shared.b32 %0, [%1];" : "=r"(b[ni][r]) : "r"(addr));
                        }
                    }
                    #pragma unroll
                    for (int mi = 0; mi < 4; mi++)
                        #pragma unroll
                        for (int ni = 0; ni < 4; ni++)
                            MMA_BF16(acc[mi][ni], a[mi], b[ni]);
                }
                if (it + 2 < ITBF) {
                    int s2 = st + 2; if (s2 >= 3) s2 -= 3;
                    load_stage(it + 2, s2);         // writes a buffer nobody reads now
                }
                CP_COMMIT();                        // unconditional (tail-correct)
                st = (st == 2) ? 0 : st + 1;
            }

            float rs0[4], rs1[4];
            #pragma unroll
            for (int mi = 0; mi < 4; mi++) {
                int row0 = m0 + row_a + mi * 16 + (lane >> 2);
                rs0[mi] = g_rowscale[row0];
                rs1[mi] = g_rowscale[row0 + 8];
            }
            #pragma unroll
            for (int ni = 0; ni < 4; ni++) {
                int col = n0 + row_b + ni * 8 + ((lane & 3) << 1);
                float b0 = bias[col], b1 = bias[col + 1];
                #pragma unroll
                for (int mi = 0; mi < 4; mi++) {
                    int row0 = m0 + row_a + mi * 16 + (lane >> 2);
                    const float* cc = acc[mi][ni];
                    float2 v0 = make_float2(cc[0] * rs0[mi] + b0, cc[1] * rs0[mi] + b1);
                    float2 v1 = make_float2(cc[2] * rs1[mi] + b0, cc[3] * rs1[mi] + b1);
                    *reinterpret_cast<float2*>(out + (size_t)row0 * NN + col) = v0;
                    *reinterpret_cast<float2*>(out + (size_t)(row0 + 8) * NN + col) = v1;
                }
            }
        } else {
            // ---------------- s8 engine ----------------
            const int8_t* Ag = g_act8 + (size_t)m0 * KK;
            const int8_t* Bg = g_wq8 + (size_t)n0 * KK;
            int acc[4][4][4];
            #pragma unroll
            for (int i = 0; i < 4; i++)
                #pragma unroll
                for (int j = 0; j < 4; j++)
                    #pragma unroll
                    for (int k = 0; k < 4; k++) acc[i][j][k] = 0;

            auto load_stage = [&](int it, int s) {
                uint32_t As = sbase + s * STGB;
                uint32_t Bs = As + AST;
                #pragma unroll
                for (int i = 0; i < 4; i++) {
                    int cc = tid + i * 256;
                    int row = cc >> 3, u = cc & 7;
                    uint32_t so = row * 128 + ((u ^ (row & 7)) << 4);
                    CP_ASYNC16(As + so, Ag + (size_t)row * KK + it * SK8 + u * 16);
                    CP_ASYNC16(Bs + so, Bg + (size_t)row * KK + it * SK8 + u * 16);
                }
            };

            load_stage(0, 0); CP_COMMIT();
            load_stage(1, 1); CP_COMMIT();

            int st = 0;
            for (int it = 0; it < IT8; ++it) {
                CP_WAIT(1);
                __syncthreads();                    // single barrier per iteration
                uint32_t As = sbase + st * STGB;
                uint32_t Bs = As + AST;
                #pragma unroll
                for (int kk = 0; kk < 4; ++kk) {    // 4 x K=32
                    uint32_t a[4][4];
                    #pragma unroll
                    for (int mi = 0; mi < 4; mi++) {
                        int row0 = row_a + mi * 16 + (lane >> 2);
                        #pragma unroll
                        for (int r = 0; r < 4; r++) {
                            int row = row0 + ((r & 1) << 3);
                            int u = kk * 2 + (r >> 1);
                            uint32_t addr = As + row * 128 + ((u ^ (row & 7)) << 4) + ((lane & 3) << 2);
                            asm volatile("ld.shared.b32 %0, [%1];" : "=r"(a[mi][r]) : "r"(addr));
                        }
                    }
                    uint32_t b[4][2];
                    #pragma unroll
                    for (int ni = 0; ni < 4; ni++) {
                        int rowb = row_b + ni * 8 + (lane >> 2);
                        #pragma unroll
                        for (int r = 0; r < 2; r++) {
                            int u = kk * 2 + r;
                            uint32_t addr = Bs + rowb * 128 + ((u ^ (rowb & 7)) << 4) + ((lane & 3) << 2);
                            asm volatile("ld.shared.b32 %0, [%1];" : "=r"(b[ni][r]) : "r"(addr));
                        }
                    }
                    #pragma unroll
                    for (int mi = 0; mi < 4; mi++)
                        #pragma unroll
                        for (int ni = 0; ni < 4; ni++)
                            MMA_S8(acc[mi][ni], a[mi], b[ni]);
                }
                if (it + 2 < IT8) {
                    int s2 = st + 2; if (s2 >= 3) s2 -= 3;
                    load_stage(it + 2, s2);
                }
                CP_COMMIT();                        // unconditional (tail-correct)
                st = (st == 2) ? 0 : st + 1;
            }

            float rs0[4], rs1[4];
            #pragma unroll
            for (int mi = 0; mi < 4; mi++) {
                int row0 = m0 + row_a + mi * 16 + (lane >> 2);
                rs0[mi] = g_rowscale[row0];
                rs1[mi] = g_rowscale[row0 + 8];
            }
            #pragma unroll
            for (int ni = 0; ni < 4; ni++) {
                int col = n0 + row_b + ni * 8 + ((lane & 3) << 1);
                float b0 = bias[col], b1 = bias[col + 1];
                #pragma unroll
                for (int mi = 0; mi < 4; mi++) {
                    int row0 = m0 + row_a + mi * 16 + (lane >> 2);
                    const int* cc = acc[mi][ni];
                    float2 v0 = make_float2(__int2float_rn(cc[0]) * rs0[mi] + b0,
                                            __int2float_rn(cc[1]) * rs0[mi] + b1);
                    float2 v1 = make_float2(__int2float_rn(cc[2]) * rs1[mi] + b0,
                                            __int2float_rn(cc[3]) * rs1[mi] + b1);
                    *reinterpret_cast<float2*>(out + (size_t)row0 * NN + col) = v0;
                    *reinterpret_cast<float2*>(out + (size_t)(row0 + 8) * NN + col) = v1;
                }
            }
        }
        __syncthreads();    // protect s_tile rewrite + smem reuse next tile
    }
}

// ============================================================
// Host side
// ============================================================
extern "C" void kernel_launch(void* const* d_in, const int* in_sizes, int n_in,
                              void* d_out, int out_size) {
    const float* x    = (const float*)d_in[0];
    const float* w    = (const float*)d_in[1];
    const float* bias = (const float*)d_in[2];
    float* out = (float*)d_out;

    // reset tile-pool + per-SM pairing counters (graph-capturable memset)
    void* ctrp = nullptr;
    cudaGetSymbolAddress(&ctrp, g_ctr);
    cudaMemsetAsync(ctrp, 0, sizeof(unsigned) * 260, 0);

    wabs_kernel<<<NN, 256>>>(w);
    wfinal_kernel<<<1, 256>>>();
    ternarize_kernel<<<(NN * KK / 4) / 256, 256>>>(w);
    ln_quant_kernel<<<MM, 128>>>(x);

    static bool attr_set = false;
    if (!attr_set) {
        cudaFuncSetAttribute(gemm_pers_kernel, cudaFuncAttributeMaxDynamicSharedMemorySize, GEMM_SMEM);
        attr_set = true;
    }
    gemm_pers_kernel<<<NPERS, 256, GEMM_SMEM>>>(bias, out);
}